// round 10
// baseline (speedup 1.0000x reference)
#include <cuda_runtime.h>

#define NN 100000
#define EE 1600000
#define NPB 1024                          // nodes per bucket (power of 2)
#define NBMAX ((NN + NPB - 1) / NPB)      // 98
#define CHUNK 2048                        // edges per partition block (= 256 thr * 8)
#define BPB 8                             // blocks per bucket in scatter passes
#define BLK 256

// ---- device scratch (no allocations allowed) ----
__device__ int2   g_part[EE];             // edges partitioned by dst bucket
__device__ int    g_bcnt[NBMAX];
__device__ int    g_bbase[NBMAX + 1];
__device__ int    g_bcur[NBMAX];          // re-armed every launch by k_scan
__device__ float  g_dinv[NN];
__device__ float  g_px[NN];               // dinv[v]*x[v]
__device__ float  g_s[NN];                // raw then finalized layer-1 value
__device__ float2 g_pq[NN];               // dinv[v]*(max(s,0), min(s,0))
__device__ float2 g_PQ[NN];               // layer-2 (P,Q) aggregate incl. self term
__device__ float  g_agg[NN * 16];         // fallback (b1 != 0) aggregate
__device__ float  g_c[64];                // c1=relu(W1)@W2, c2=min(W1,0)@W2
__device__ int    g_b1zero, g_is64;

__device__ __forceinline__ void red2(float2* addr, float2 v) {
    asm volatile("red.add.v2.f32 [%0], {%1, %2};"
                 :: "l"(addr), "f"(v.x), "f"(v.y) : "memory");
}

__device__ __forceinline__ int bucket_of(int d, int NB) {
    unsigned b = ((unsigned)d) >> 10;          // defensive: clamp, never OOB
    return (b < (unsigned)NB) ? (int)b : NB - 1;
}

// ---- setup: dtype probe, b1 flag, fused coefs, zero counters/fallback ----
__global__ void k_setup(const void* __restrict__ ei, const float* __restrict__ W1,
                        const float* __restrict__ b1, const float* __restrict__ W2,
                        int E, int N, int NB) {
    int tid = threadIdx.x;
    int gid = blockIdx.x * BLK + tid;
    if (blockIdx.x == 0) {
        __shared__ int bad;
        if (tid == 0) bad = 0;
        __syncthreads();
        if (tid < E) {
            long long v = ((const long long*)ei)[tid];  // first 256 slots in-bounds both layouts
            if (v < 0 || v >= (long long)N) atomicExch(&bad, 1);
        }
        __syncthreads();
        if (tid == 0) {
            g_is64 = !bad;
            int z = 1;
            for (int k = 0; k < 16; k++)
                if (b1[k] != 0.f) z = 0;
            g_b1zero = z;
        }
        if (tid < 32) {
            float c1 = 0.f, c2 = 0.f;
#pragma unroll
            for (int k = 0; k < 16; k++) {
                float w  = W1[k];
                float wv = W2[k * 32 + tid];
                c1 += fmaxf(w, 0.f) * wv;
                c2 += fminf(w, 0.f) * wv;
            }
            g_c[tid] = c1;
            g_c[32 + tid] = c2;
        }
    }
    if (gid < NB) g_bcnt[gid] = 0;
    if (gid < N) {
        bool bz = true;
#pragma unroll
        for (int k = 0; k < 16; k++)
            if (b1[k] != 0.f) bz = false;
        if (!bz) {
            float4 z = make_float4(0.f, 0.f, 0.f, 0.f);
            float4* a = reinterpret_cast<float4*>(&g_agg[(size_t)gid * 16]);
            a[0] = z; a[1] = z; a[2] = z; a[3] = z;
        }
    }
}

// ---- bucket histogram over dst stream ----
__global__ void k_hist(const void* __restrict__ eiv, int E, int NB) {
    __shared__ int sh[NBMAX];
    int tid = threadIdx.x;
    for (int i = tid; i < NB; i += blockDim.x) sh[i] = 0;
    __syncthreads();
    int stride = gridDim.x * blockDim.x;
    int g0 = blockIdx.x * blockDim.x + tid;
    if (g_is64) {
        const long long* dst = (const long long*)eiv + E;
        for (int e = g0; e < E; e += stride)
            atomicAdd(&sh[bucket_of((int)dst[e], NB)], 1);
    } else {
        const int* dst = (const int*)eiv + E;
        for (int e = g0; e < E; e += stride)
            atomicAdd(&sh[bucket_of(dst[e], NB)], 1);
    }
    __syncthreads();
    for (int i = tid; i < NB; i += blockDim.x)
        if (sh[i]) atomicAdd(&g_bcnt[i], sh[i]);
}

// ---- tiny exact scan (NB <= 98), single thread ----
__global__ void k_scan(int E, int NB) {
    if (threadIdx.x == 0 && blockIdx.x == 0) {
        int run = 0;
        for (int b = 0; b < NB; b++) {
            g_bbase[b] = run;
            g_bcur[b]  = run;
            run += g_bcnt[b];
        }
        g_bbase[NB] = run;   // == E
    }
}

// ---- partition: register-staged, bucket-sorted smem, coalesced writeout ----
__global__ void __launch_bounds__(256) k_part(const void* __restrict__ eiv, int E, int NB) {
    __shared__ int2 se2[CHUNK];              // 16 KB (bucket-sorted edges)
    __shared__ int scnt[NBMAX];
    __shared__ int cbase[NBMAX];
    __shared__ int sbase[NBMAX];
    int tid = threadIdx.x;
    for (int i = tid; i < NB; i += 256) scnt[i] = 0;
    __syncthreads();
    int e0 = blockIdx.x * CHUNK;
    int cnt = min(CHUNK, E - e0);
    int is64 = g_is64;

    // pass A: load 8 edges/thread into registers, take per-bucket ranks
    int rs[8], rd[8], rr[8];
#pragma unroll
    for (int k = 0; k < 8; k++) {
        int i = tid + k * 256;
        rr[k] = -1;
        if (i < cnt) {
            int s, d;
            if (is64) {
                const long long* sp = (const long long*)eiv;
                s = (int)sp[e0 + i];
                d = (int)sp[E + e0 + i];
            } else {
                const int* sp = (const int*)eiv;
                s = sp[e0 + i];
                d = sp[E + e0 + i];
            }
            rs[k] = s; rd[k] = d;
            rr[k] = atomicAdd(&scnt[bucket_of(d, NB)], 1);
        }
    }
    __syncthreads();
    // chunk-local exclusive scan (thread 0), then global reservations
    if (tid == 0) {
        int run = 0;
        for (int b = 0; b < NB; b++) { cbase[b] = run; run += scnt[b]; }
    }
    __syncthreads();
    if (tid < NB)
        sbase[tid] = atomicAdd(&g_bcur[tid], scnt[tid]);
    __syncthreads();
    // pass B: place register-held edges bucket-sorted into smem
#pragma unroll
    for (int k = 0; k < 8; k++) {
        if (rr[k] >= 0)
            se2[cbase[bucket_of(rd[k], NB)] + rr[k]] = make_int2(rs[k], rd[k]);
    }
    __syncthreads();
    // pass C: per-warp contiguous segment copy to global
    int warp = tid >> 5, lane = tid & 31;
    for (int b = warp; b < NB; b += 8) {
        int n = scnt[b], cb = cbase[b], gb = sbase[b];
        for (int k = lane; k < n; k += 32)
            g_part[gb + k] = se2[cb + k];
    }
}

// ---- fused: exact bucket degree + dinv + px + s-init (1 block per bucket) ----
__global__ void __launch_bounds__(256) k_degpx(const float* __restrict__ x, int N) {
    __shared__ int sdeg[NPB];
    int tid = threadIdx.x, b = blockIdx.x;
    for (int l = tid; l < NPB; l += 256) sdeg[l] = 0;
    __syncthreads();
    int lo = g_bbase[b], hi = g_bbase[b + 1];
    for (int i = lo + tid; i < hi; i += 256)
        atomicAdd(&sdeg[g_part[i].y & (NPB - 1)], 1);
    __syncthreads();
    for (int l = tid; l < NPB; l += 256) {
        int v = b * NPB + l;
        if (v < N) {
            float dv = rsqrtf((float)sdeg[l] + 1.0f);
            g_dinv[v] = dv;
            float pxv = dv * x[v];
            g_px[v] = pxv;
            g_s[v]  = pxv;   // self-loop contribution to raw sum
        }
    }
}

// ---- layer-1 scatter: smem accumulate + coalesced flush (BPB blocks/bucket) ----
__global__ void __launch_bounds__(256) k_scat1(int N) {
    __shared__ float sacc[NPB];   // 4 KB
    int tid = threadIdx.x;
    int b = blockIdx.x / BPB, j = blockIdx.x % BPB;
    for (int l = tid; l < NPB; l += 256) sacc[l] = 0.f;
    __syncthreads();
    int lo = g_bbase[b], hi = g_bbase[b + 1], len = hi - lo;
    int s0 = lo + (int)((long long)len * j / BPB);
    int s1 = lo + (int)((long long)len * (j + 1) / BPB);
    for (int i = s0 + tid; i < s1; i += 256) {
        int2 e = g_part[i];
        atomicAdd(&sacc[e.y & (NPB - 1)], __ldg(&g_px[e.x]));
    }
    __syncthreads();
    for (int l = tid; l < NPB; l += 256) {
        int v = b * NPB + l;
        if (v < N && sacc[l] != 0.f) atomicAdd(&g_s[v], sacc[l]);
    }
}

// ---- finalize s; pq split; PQ init = self term ----
__global__ void k_node2(int n) {
    int v = blockIdx.x * blockDim.x + threadIdx.x;
    if (v >= n) return;
    float dv = g_dinv[v];
    float s  = dv * g_s[v];
    g_s[v]   = s;
    float p = fmaxf(s, 0.f), q = fminf(s, 0.f);
    float2 pq = make_float2(dv * p, dv * q);
    g_pq[v] = pq;
    g_PQ[v] = pq;
}

// ---- layer-2 scatter: smem (P,Q) accumulate + coalesced v2-RED flush ----
__global__ void __launch_bounds__(256) k_scat2(const float* __restrict__ W1,
                                               const float* __restrict__ b1, int N) {
    __shared__ float sP[NPB], sQ[NPB];   // 8 KB
    int bz = g_b1zero;
    int tid = threadIdx.x;
    int b = blockIdx.x / BPB, j = blockIdx.x % BPB;
    int lo = g_bbase[b], hi = g_bbase[b + 1], len = hi - lo;
    int s0 = lo + (int)((long long)len * j / BPB);
    int s1 = lo + (int)((long long)len * (j + 1) / BPB);
    if (bz) {
        for (int l = tid; l < NPB; l += 256) { sP[l] = 0.f; sQ[l] = 0.f; }
        __syncthreads();
        for (int i = s0 + tid; i < s1; i += 256) {
            int2 e = g_part[i];
            float2 t = __ldg(&g_pq[e.x]);
            int l = e.y & (NPB - 1);
            atomicAdd(&sP[l], t.x);
            atomicAdd(&sQ[l], t.y);
        }
        __syncthreads();
        for (int l = tid; l < NPB; l += 256) {
            int v = b * NPB + l;
            if (v < N) {
                float p = sP[l], q = sQ[l];
                if (p != 0.f || q != 0.f) red2(&g_PQ[v], make_float2(p, q));
            }
        }
    } else {
        __shared__ float sW1[16], sb1[16];
        if (tid < 16) { sW1[tid] = W1[tid]; sb1[tid] = b1[tid]; }
        __syncthreads();
        for (int i = s0 + tid; i < s1; i += 256) {
            int2 e = g_part[i];
            float sv = __ldg(&g_s[e.x]);
            float ns = __ldg(&g_dinv[e.x]);
#pragma unroll
            for (int k = 0; k < 16; k++) {
                float h = fmaxf(sv * sW1[k] + sb1[k], 0.f);
                atomicAdd(&g_agg[(size_t)e.y * 16 + k], ns * h);
            }
        }
    }
}

// ---- output projection ----
__global__ void k_out(const float* __restrict__ W1, const float* __restrict__ b1,
                      const float* __restrict__ W2, const float* __restrict__ b2,
                      float* __restrict__ out, int n) {
    __shared__ float sc[64];
    __shared__ float sb2[32];
    __shared__ float sW2[512];
    __shared__ float sW1[16], sb1[16];
    int bz = g_b1zero;
    int t = threadIdx.x;
    if (t < 64) sc[t] = g_c[t];
    if (t < 32) sb2[t] = b2[t];
    if (!bz) {
        for (int k = t; k < 512; k += blockDim.x) sW2[k] = W2[k];
        if (t < 16) { sW1[t] = W1[t]; sb1[t] = b1[t]; }
    }
    __syncthreads();
    int v = blockIdx.x * blockDim.x + t;
    if (v >= n) return;

    float o[32];
    float dv = g_dinv[v];
    if (bz) {
        float2 PQ = g_PQ[v];
        float P = dv * PQ.x, Q = dv * PQ.y;
#pragma unroll
        for (int j = 0; j < 32; j++) o[j] = P * sc[j] + Q * sc[32 + j] + sb2[j];
    } else {
        float sv = g_s[v];
        float n2 = dv * dv;
        float tot[16];
#pragma unroll
        for (int k = 0; k < 16; k++) {
            float h = fmaxf(sv * sW1[k] + sb1[k], 0.f);
            tot[k] = dv * g_agg[(size_t)v * 16 + k] + n2 * h;
        }
#pragma unroll
        for (int j = 0; j < 32; j++) {
            float acc = sb2[j];
#pragma unroll
            for (int k = 0; k < 16; k++) acc += tot[k] * sW2[k * 32 + j];
            o[j] = acc;
        }
    }
    float4* po = reinterpret_cast<float4*>(out + (size_t)v * 32);
#pragma unroll
    for (int j = 0; j < 8; j++)
        __stcs(po + j, make_float4(o[4 * j], o[4 * j + 1], o[4 * j + 2], o[4 * j + 3]));
}

extern "C" void kernel_launch(void* const* d_in, const int* in_sizes, int n_in,
                              void* d_out, int out_size) {
    const float* x  = (const float*)d_in[0];
    const void*  ei = d_in[1];
    const float* W1 = (const float*)d_in[2];
    const float* b1 = (const float*)d_in[3];
    const float* W2 = (const float*)d_in[4];
    const float* b2 = (const float*)d_in[5];
    float* out = (float*)d_out;

    int N = in_sizes[0];
    int E = in_sizes[1] / 2;
    int NB = (N + NPB - 1) / NPB;   // <= NBMAX

    int gN    = (N + BLK - 1) / BLK;
    int gPart = (E + CHUNK - 1) / CHUNK;

    k_setup<<<gN, BLK>>>(ei, W1, b1, W2, E, N, NB);
    k_hist<<<296, BLK>>>(ei, E, NB);
    k_scan<<<1, 32>>>(E, NB);
    k_part<<<gPart, BLK>>>(ei, E, NB);
    k_degpx<<<NB, BLK>>>(x, N);
    k_scat1<<<NB * BPB, BLK>>>(N);
    k_node2<<<gN, BLK>>>(N);
    k_scat2<<<NB * BPB, BLK>>>(W1, b1, N);
    k_out<<<gN, BLK>>>(W1, b1, W2, b2, out, N);
}

// round 11
// speedup vs baseline: 1.1470x; 1.1470x over previous
#include <cuda_runtime.h>

#define NN 100000
#define EE 1600000
#define BLK 256

// ---- device scratch (zero-initialized at module load; each kernel restores
//      the zero invariant it consumes, so graph replays stay deterministic) ----
__device__ int    g_src32[EE];
__device__ int    g_dst32[EE];
__device__ float  g_deg[NN];       // zeroed by k_node1 after use
__device__ float  g_dinv[NN];
__device__ float  g_px[NN];
__device__ float  g_s[NN];
__device__ float2 g_pq[NN];
__device__ float2 g_PQ[NN];
__device__ float  g_agg[NN * 16];  // fallback; zeroed by k_out after use
__device__ float  g_c[64];
__device__ int    g_b1zero;
__device__ int    g_is64;

__device__ __forceinline__ int4 ldcs4(const int* p) {
    return __ldcs(reinterpret_cast<const int4*>(p));
}

__device__ __forceinline__ void red2(float2* addr, float2 v) {
    asm volatile("red.add.v2.f32 [%0], {%1, %2};"
                 :: "l"(addr), "f"(v.x), "f"(v.y) : "memory");
}

// ---- setup: dtype probe + fused coefficients (single block) ----
__global__ void k_setup(const void* __restrict__ ei, const float* __restrict__ W1,
                        const float* __restrict__ b1, const float* __restrict__ W2,
                        int E, int N) {
    int tid = threadIdx.x;
    __shared__ int bad;
    if (tid == 0) bad = 0;
    __syncthreads();
    if (tid < E) {
        long long v = ((const long long*)ei)[tid];  // first 256 slots in-bounds both layouts
        if (v < 0 || v >= (long long)N) atomicExch(&bad, 1);
    }
    __syncthreads();
    if (tid == 0) {
        g_is64 = !bad;
        int z = 1;
        for (int k = 0; k < 16; k++)
            if (b1[k] != 0.f) z = 0;
        g_b1zero = z;
    }
    if (tid < 32) {
        float c1 = 0.f, c2 = 0.f;
#pragma unroll
        for (int k = 0; k < 16; k++) {
            float w  = W1[k];
            float wv = W2[k * 32 + tid];
            c1 += fmaxf(w, 0.f) * wv;
            c2 += fminf(w, 0.f) * wv;
        }
        g_c[tid] = c1;
        g_c[32 + tid] = c2;
    }
}

// ---- pass 1: degree REDs (+ one-time int64->int32 conversion), 8 edges/thread ----
__global__ void __launch_bounds__(BLK) k_deg(const void* __restrict__ eiv, int E) {
    int e0 = 8 * (blockIdx.x * blockDim.x + threadIdx.x);
    if (e0 >= E) return;
    if (g_is64) {
        const long long* ei = (const long long*)eiv;
        if (e0 + 7 < E) {
#pragma unroll
            for (int h = 0; h < 2; h++) {
                int b = e0 + 4 * h;
                longlong2 sA = __ldcs(reinterpret_cast<const longlong2*>(ei + b));
                longlong2 sB = __ldcs(reinterpret_cast<const longlong2*>(ei + b + 2));
                longlong2 dA = __ldcs(reinterpret_cast<const longlong2*>(ei + E + b));
                longlong2 dB = __ldcs(reinterpret_cast<const longlong2*>(ei + E + b + 2));
                int4 sv = make_int4((int)sA.x, (int)sA.y, (int)sB.x, (int)sB.y);
                int4 dv = make_int4((int)dA.x, (int)dA.y, (int)dB.x, (int)dB.y);
                *reinterpret_cast<int4*>(&g_src32[b]) = sv;
                *reinterpret_cast<int4*>(&g_dst32[b]) = dv;
                atomicAdd(&g_deg[dv.x], 1.f); atomicAdd(&g_deg[dv.y], 1.f);
                atomicAdd(&g_deg[dv.z], 1.f); atomicAdd(&g_deg[dv.w], 1.f);
            }
        } else {
            for (int e = e0; e < E; e++) {
                int s = (int)ei[e], d = (int)ei[E + e];
                g_src32[e] = s; g_dst32[e] = d;
                atomicAdd(&g_deg[d], 1.f);
            }
        }
    } else {
        const int* dst = (const int*)eiv + E;
        if (e0 + 7 < E) {
            int4 d0 = ldcs4(dst + e0);
            int4 d1 = ldcs4(dst + e0 + 4);
            atomicAdd(&g_deg[d0.x], 1.f); atomicAdd(&g_deg[d0.y], 1.f);
            atomicAdd(&g_deg[d0.z], 1.f); atomicAdd(&g_deg[d0.w], 1.f);
            atomicAdd(&g_deg[d1.x], 1.f); atomicAdd(&g_deg[d1.y], 1.f);
            atomicAdd(&g_deg[d1.z], 1.f); atomicAdd(&g_deg[d1.w], 1.f);
        } else {
            for (int e = e0; e < E; e++) atomicAdd(&g_deg[dst[e]], 1.f);
        }
    }
}

// ---- pass 2: dinv; px; raw s init; restore g_deg zero invariant ----
__global__ void k_node1(const float* __restrict__ x, int n) {
    int v = blockIdx.x * blockDim.x + threadIdx.x;
    if (v >= n) return;
    float dg = g_deg[v];
    g_deg[v] = 0.f;                    // reset for next graph replay
    float dv  = rsqrtf(dg + 1.0f);
    g_dinv[v] = dv;
    float pxv = dv * x[v];
    g_px[v]   = pxv;
    g_s[v]    = pxv;                   // self-loop contribution to raw sum
}

// ---- pass 3: layer-1 raw scatter, 4 edges/thread (proven best config) ----
__global__ void __launch_bounds__(BLK) k_scat1(const void* __restrict__ eiv, int E) {
    const int* srcp = g_is64 ? g_src32 : (const int*)eiv;
    const int* dstp = g_is64 ? g_dst32 : (const int*)eiv + E;
    int e0 = 4 * (blockIdx.x * blockDim.x + threadIdx.x);
    if (e0 >= E) return;
    if (e0 + 3 < E) {
        int4 s = ldcs4(srcp + e0);
        int4 d = ldcs4(dstp + e0);
        float a0 = __ldg(&g_px[s.x]), a1 = __ldg(&g_px[s.y]);
        float a2 = __ldg(&g_px[s.z]), a3 = __ldg(&g_px[s.w]);
        atomicAdd(&g_s[d.x], a0); atomicAdd(&g_s[d.y], a1);
        atomicAdd(&g_s[d.z], a2); atomicAdd(&g_s[d.w], a3);
    } else {
        for (int e = e0; e < E; e++)
            atomicAdd(&g_s[dstp[e]], __ldg(&g_px[srcp[e]]));
    }
}

// ---- pass 4: finalize s; pq split; PQ init = self term ----
__global__ void k_node2(int n) {
    int v = blockIdx.x * blockDim.x + threadIdx.x;
    if (v >= n) return;
    float dv = g_dinv[v];
    float s  = dv * g_s[v];
    g_s[v]   = s;
    float p = fmaxf(s, 0.f), q = fminf(s, 0.f);
    float2 pq = make_float2(dv * p, dv * q);
    g_pq[v] = pq;
    g_PQ[v] = pq;
}

// ---- pass 5: layer-2 raw scatter, 4 edges/thread, 1 v2-RED/edge ----
__global__ void __launch_bounds__(BLK) k_scat2(const void* __restrict__ eiv,
                                               const float* __restrict__ W1,
                                               const float* __restrict__ b1, int E) {
    const int* srcp = g_is64 ? g_src32 : (const int*)eiv;
    const int* dstp = g_is64 ? g_dst32 : (const int*)eiv + E;
    int bz = g_b1zero;
    int e0 = 4 * (blockIdx.x * blockDim.x + threadIdx.x);
    if (e0 >= E) return;
    if (bz) {
        if (e0 + 3 < E) {
            int4 s = ldcs4(srcp + e0);
            int4 d = ldcs4(dstp + e0);
            float2 t0 = __ldg(&g_pq[s.x]), t1 = __ldg(&g_pq[s.y]);
            float2 t2 = __ldg(&g_pq[s.z]), t3 = __ldg(&g_pq[s.w]);
            red2(&g_PQ[d.x], t0); red2(&g_PQ[d.y], t1);
            red2(&g_PQ[d.z], t2); red2(&g_PQ[d.w], t3);
        } else {
            for (int e = e0; e < E; e++) red2(&g_PQ[dstp[e]], __ldg(&g_pq[srcp[e]]));
        }
    } else {
        __shared__ float sW1[16], sb1[16];
        if (threadIdx.x < 16) { sW1[threadIdx.x] = W1[threadIdx.x]; sb1[threadIdx.x] = b1[threadIdx.x]; }
        __syncthreads();
        int eEnd = min(e0 + 4, E);
        for (int e = e0; e < eEnd; e++) {
            int s = srcp[e], d = dstp[e];
            float sv = __ldg(&g_s[s]);
            float ns = __ldg(&g_dinv[s]);
#pragma unroll
            for (int k = 0; k < 16; k++) {
                float h = fmaxf(sv * sW1[k] + sb1[k], 0.f);
                atomicAdd(&g_agg[(size_t)d * 16 + k], ns * h);
            }
        }
    }
}

// ---- pass 6: output projection (fallback path restores g_agg zero invariant) ----
__global__ void k_out(const float* __restrict__ W1, const float* __restrict__ b1,
                      const float* __restrict__ W2, const float* __restrict__ b2,
                      float* __restrict__ out, int n) {
    __shared__ float sc[64];
    __shared__ float sb2[32];
    __shared__ float sW2[512];
    __shared__ float sW1[16], sb1[16];
    int bz = g_b1zero;
    int t = threadIdx.x;
    if (t < 64) sc[t] = g_c[t];
    if (t < 32) sb2[t] = b2[t];
    if (!bz) {
        for (int k = t; k < 512; k += blockDim.x) sW2[k] = W2[k];
        if (t < 16) { sW1[t] = W1[t]; sb1[t] = b1[t]; }
    }
    __syncthreads();
    int v = blockIdx.x * blockDim.x + t;
    if (v >= n) return;

    float o[32];
    float dv = g_dinv[v];
    if (bz) {
        float2 PQ = g_PQ[v];
        float P = dv * PQ.x, Q = dv * PQ.y;
#pragma unroll
        for (int j = 0; j < 32; j++) o[j] = P * sc[j] + Q * sc[32 + j] + sb2[j];
    } else {
        float sv = g_s[v];
        float n2 = dv * dv;
        float tot[16];
        float4* a = reinterpret_cast<float4*>(&g_agg[(size_t)v * 16]);
        float4 z = make_float4(0.f, 0.f, 0.f, 0.f);
#pragma unroll
        for (int q4 = 0; q4 < 4; q4++) {
            float4 av = a[q4];
            a[q4] = z;                 // reset invariant for next replay
            tot[4 * q4 + 0] = av.x; tot[4 * q4 + 1] = av.y;
            tot[4 * q4 + 2] = av.z; tot[4 * q4 + 3] = av.w;
        }
#pragma unroll
        for (int k = 0; k < 16; k++) {
            float h = fmaxf(sv * sW1[k] + sb1[k], 0.f);
            tot[k] = dv * tot[k] + n2 * h;
        }
#pragma unroll
        for (int j = 0; j < 32; j++) {
            float acc = sb2[j];
#pragma unroll
            for (int k = 0; k < 16; k++) acc += tot[k] * sW2[k * 32 + j];
            o[j] = acc;
        }
    }
    float4* po = reinterpret_cast<float4*>(out + (size_t)v * 32);
#pragma unroll
    for (int j = 0; j < 8; j++)
        __stcs(po + j, make_float4(o[4 * j], o[4 * j + 1], o[4 * j + 2], o[4 * j + 3]));
}

extern "C" void kernel_launch(void* const* d_in, const int* in_sizes, int n_in,
                              void* d_out, int out_size) {
    const float* x  = (const float*)d_in[0];
    const void*  ei = d_in[1];
    const float* W1 = (const float*)d_in[2];
    const float* b1 = (const float*)d_in[3];
    const float* W2 = (const float*)d_in[4];
    const float* b2 = (const float*)d_in[5];
    float* out = (float*)d_out;

    int N = in_sizes[0];
    int E = in_sizes[1] / 2;

    int gN  = (N + BLK - 1) / BLK;
    int gE4 = ((E + 3) / 4 + BLK - 1) / BLK;
    int gE8 = ((E + 7) / 8 + BLK - 1) / BLK;

    k_setup<<<1, BLK>>>(ei, W1, b1, W2, E, N);
    k_deg<<<gE8, BLK>>>(ei, E);
    k_node1<<<gN, BLK>>>(x, N);
    k_scat1<<<gE4, BLK>>>(ei, E);
    k_node2<<<gN, BLK>>>(N);
    k_scat2<<<gE4, BLK>>>(ei, W1, b1, E);
    k_out<<<gN, BLK>>>(W1, b1, W2, b2, out, N);
}